// round 1
// baseline (speedup 1.0000x reference)
#include <cuda_runtime.h>
#include <math.h>

// Problem constants (fixed by the reference: B=32, N=4096, D=512, K=64, no ghost clusters)
#define Bb 32
#define Nn 4096
#define Dd 512
#define Kk 64

// Scratch (device globals — no allocation allowed)
__device__ float g_assign[(size_t)Bb * Nn * Kk];   // 32 MB: softmax assignments [b,n,k]
__device__ float g_vlad[(size_t)Bb * Kk * Dd];     // 4 MB: raw vlad, stored [b,k,d]
__device__ float g_asum[Bb * Kk];                  // per-(b,k) assignment sums
__device__ float g_gnormsq[Bb];                    // per-batch squared norm after intra-norm

// ---------------------------------------------------------------------------
// k0: zero the accumulators (graph replays require re-zero every launch)
// ---------------------------------------------------------------------------
__global__ void k0_init() {
    int i = blockIdx.x * 256 + threadIdx.x;
    if (i < Bb * Kk) g_asum[i] = 0.0f;
    if (i < Bb)      g_gnormsq[i] = 0.0f;
}

// ---------------------------------------------------------------------------
// k1: logits = x_flat @ clusters  (131072x512 @ 512x64), fused BN(eval) +
//     softmax + write assignment + atomic a_sum.
// One block = 64 rows x all 64 cluster columns. 256 threads, 4x4 microtile.
// ---------------------------------------------------------------------------
__global__ __launch_bounds__(256) void k1_logits_softmax(
    const float* __restrict__ x,
    const float* __restrict__ clusters,
    const float* __restrict__ bnw,
    const float* __restrict__ bnb,
    const float* __restrict__ rm,
    const float* __restrict__ rv)
{
    __shared__ float xs[64 * 68];    // x tile [row][d], padded stride 68
    __shared__ float cs[64 * 64];    // clusters tile [d][k]
    __shared__ float redbuf[4 * 64];
    __shared__ float invs[64];

    const int tid  = threadIdx.x;
    const int row0 = blockIdx.x * 64;
    const int ty = tid >> 4;         // 0..15 -> rows ty*4..ty*4+3
    const int tx = tid & 15;         // 0..15 -> cols tx*4..tx*4+3

    float acc[4][4];
#pragma unroll
    for (int i = 0; i < 4; i++)
#pragma unroll
        for (int j = 0; j < 4; j++) acc[i][j] = 0.0f;

    const int lr = tid >> 4;
    const int lc = (tid & 15) * 4;
    const float* xg = x + (size_t)row0 * Dd;

    for (int d0 = 0; d0 < Dd; d0 += 64) {
#pragma unroll
        for (int p = 0; p < 4; p++) {
            int r = lr + p * 16;
            *(float4*)&xs[r * 68 + lc] = *(const float4*)&xg[(size_t)r * Dd + d0 + lc];
            *(float4*)&cs[r * 64 + lc] = *(const float4*)&clusters[(size_t)(d0 + r) * Kk + lc];
        }
        __syncthreads();
#pragma unroll
        for (int kk = 0; kk < 64; kk++) {
            float a0 = xs[(ty * 4 + 0) * 68 + kk];
            float a1 = xs[(ty * 4 + 1) * 68 + kk];
            float a2 = xs[(ty * 4 + 2) * 68 + kk];
            float a3 = xs[(ty * 4 + 3) * 68 + kk];
            float4 bv = *(float4*)&cs[kk * 64 + tx * 4];
            acc[0][0] += a0 * bv.x; acc[0][1] += a0 * bv.y; acc[0][2] += a0 * bv.z; acc[0][3] += a0 * bv.w;
            acc[1][0] += a1 * bv.x; acc[1][1] += a1 * bv.y; acc[1][2] += a1 * bv.z; acc[1][3] += a1 * bv.w;
            acc[2][0] += a2 * bv.x; acc[2][1] += a2 * bv.y; acc[2][2] += a2 * bv.z; acc[2][3] += a2 * bv.w;
            acc[3][0] += a3 * bv.x; acc[3][1] += a3 * bv.y; acc[3][2] += a3 * bv.z; acc[3][3] += a3 * bv.w;
        }
        __syncthreads();
    }

    // BN affine per output column
    float sc[4], sh[4];
#pragma unroll
    for (int j = 0; j < 4; j++) {
        int k = tx * 4 + j;
        float istd = rsqrtf(rv[k] + 1e-5f);
        sc[j] = bnw[k] * istd;
        sh[j] = bnb[k] - rm[k] * sc[j];
    }
    // store BN'd logits to smem (reuse xs region, stride 65; 64*65=4160 <= 64*68)
#pragma unroll
    for (int i = 0; i < 4; i++)
#pragma unroll
        for (int j = 0; j < 4; j++)
            xs[(ty * 4 + i) * 65 + tx * 4 + j] = acc[i][j] * sc[j] + sh[j];
    __syncthreads();

    // row softmax: thread r handles row r
    if (tid < 64) {
        float m = -1e30f;
#pragma unroll 8
        for (int k = 0; k < 64; k++) m = fmaxf(m, xs[tid * 65 + k]);
        float s = 0.0f;
#pragma unroll 8
        for (int k = 0; k < 64; k++) {
            float e = __expf(xs[tid * 65 + k] - m);
            xs[tid * 65 + k] = e;
            s += e;
        }
        invs[tid] = 1.0f / s;
    }
    __syncthreads();

    // cooperative coalesced write of assignment + per-k partial sums
    float part = 0.0f;
    const int kcol = tid & 63;
    float* ag = g_assign + (size_t)row0 * Kk;
#pragma unroll
    for (int j = 0; j < 16; j++) {
        int r = (tid >> 6) + j * 4;
        float v = xs[r * 65 + kcol] * invs[r];
        ag[(size_t)r * Kk + kcol] = v;
        part += v;
    }
    redbuf[(tid >> 6) * 64 + kcol] = part;
    __syncthreads();
    if (tid < 64) {
        float s = redbuf[tid] + redbuf[64 + tid] + redbuf[128 + tid] + redbuf[192 + tid];
        atomicAdd(&g_asum[(row0 >> 12) * Kk + tid], s);
    }
}

// ---------------------------------------------------------------------------
// k2: per-batch vlad_raw[b,d,k] = sum_n assignment[b,n,k] * x[b,n,d]
// Block = (one batch b, one 64-wide d tile) x all 64 k. Stored as [b,k,d].
// ---------------------------------------------------------------------------
__global__ __launch_bounds__(256) void k2_vlad(const float* __restrict__ x)
{
    __shared__ float xs[64 * 68];   // [n][d] padded
    __shared__ float as[64 * 64];   // [n][k]

    const int b  = blockIdx.y;
    const int d0 = blockIdx.x * 64;
    const int tid = threadIdx.x;
    const int ty = tid >> 4;        // d micro index
    const int tx = tid & 15;        // k micro index

    float acc[4][4];
#pragma unroll
    for (int i = 0; i < 4; i++)
#pragma unroll
        for (int j = 0; j < 4; j++) acc[i][j] = 0.0f;

    const int lr = tid >> 4;
    const int lc = (tid & 15) * 4;
    const float* xg = x + (size_t)b * Nn * Dd;
    const float* ag = g_assign + (size_t)b * Nn * Kk;

    for (int n0 = 0; n0 < Nn; n0 += 64) {
#pragma unroll
        for (int p = 0; p < 4; p++) {
            int r = lr + p * 16;
            *(float4*)&xs[r * 68 + lc] = *(const float4*)&xg[(size_t)(n0 + r) * Dd + d0 + lc];
            *(float4*)&as[r * 64 + lc] = *(const float4*)&ag[(size_t)(n0 + r) * Kk + lc];
        }
        __syncthreads();
#pragma unroll
        for (int nn = 0; nn < 64; nn++) {
            float a0 = xs[nn * 68 + ty * 4 + 0];
            float a1 = xs[nn * 68 + ty * 4 + 1];
            float a2 = xs[nn * 68 + ty * 4 + 2];
            float a3 = xs[nn * 68 + ty * 4 + 3];
            float4 bv = *(float4*)&as[nn * 64 + tx * 4];
            acc[0][0] += a0 * bv.x; acc[0][1] += a0 * bv.y; acc[0][2] += a0 * bv.z; acc[0][3] += a0 * bv.w;
            acc[1][0] += a1 * bv.x; acc[1][1] += a1 * bv.y; acc[1][2] += a1 * bv.z; acc[1][3] += a1 * bv.w;
            acc[2][0] += a2 * bv.x; acc[2][1] += a2 * bv.y; acc[2][2] += a2 * bv.z; acc[2][3] += a2 * bv.w;
            acc[3][0] += a3 * bv.x; acc[3][1] += a3 * bv.y; acc[3][2] += a3 * bv.z; acc[3][3] += a3 * bv.w;
        }
        __syncthreads();
    }

    // write transposed as [b][k][d]: 4 consecutive d per (k) -> float4
#pragma unroll
    for (int j = 0; j < 4; j++) {
        float4 v = make_float4(acc[0][j], acc[1][j], acc[2][j], acc[3][j]);
        *(float4*)&g_vlad[((size_t)b * Kk + tx * 4 + j) * Dd + d0 + ty * 4] = v;
    }
}

// ---------------------------------------------------------------------------
// k3: per-(b,k) column: subtract a_sum*clusters2, intra-normalize over D,
//     write to output layout [b, d*K+k], accumulate global sumsq.
// ---------------------------------------------------------------------------
__global__ __launch_bounds__(128) void k3_colnorm(const float* __restrict__ c2,
                                                  float* __restrict__ out)
{
    const int bk = blockIdx.x;          // b*64 + k
    const int b = bk >> 6;
    const int k = bk & 63;
    const int tid = threadIdx.x;

    const float a = g_asum[bk];
    const float* vr = g_vlad + (size_t)bk * Dd;

    float v[4];
    float ss = 0.0f;
#pragma unroll
    for (int p = 0; p < 4; p++) {
        int d = tid + p * 128;
        float t = vr[d] - a * c2[(size_t)d * Kk + k];
        v[p] = t;
        ss += t * t;
    }
#pragma unroll
    for (int o = 16; o; o >>= 1) ss += __shfl_xor_sync(0xffffffffu, ss, o);

    __shared__ float sred[4];
    if ((tid & 31) == 0) sred[tid >> 5] = ss;
    __syncthreads();
    float tot = sred[0] + sred[1] + sred[2] + sred[3];
    float inv = 1.0f / fmaxf(sqrtf(tot), 1e-12f);
    if (tid == 0) atomicAdd(&g_gnormsq[b], tot * inv * inv);

    float* ob = out + (size_t)b * (Dd * Kk);
#pragma unroll
    for (int p = 0; p < 4; p++) {
        int d = tid + p * 128;
        ob[(size_t)d * Kk + k] = v[p] * inv;
    }
}

// ---------------------------------------------------------------------------
// k4: final global L2 scale per batch
// ---------------------------------------------------------------------------
__global__ void k4_scale(float* __restrict__ out)
{
    int idx = blockIdx.x * 256 + threadIdx.x;   // total Bb*Dd*Kk = 1048576
    int b = idx >> 15;                          // Dd*Kk = 32768
    out[idx] *= 1.0f / fmaxf(sqrtf(g_gnormsq[b]), 1e-12f);
}

// ---------------------------------------------------------------------------
extern "C" void kernel_launch(void* const* d_in, const int* in_sizes, int n_in,
                              void* d_out, int out_size)
{
    const float* x        = (const float*)d_in[0];
    const float* clusters = (const float*)d_in[1];
    const float* c2       = (const float*)d_in[2];
    const float* bnw      = (const float*)d_in[3];
    const float* bnb      = (const float*)d_in[4];
    const float* rm       = (const float*)d_in[5];
    const float* rv       = (const float*)d_in[6];
    float* out = (float*)d_out;

    k0_init<<<8, 256>>>();
    k1_logits_softmax<<<(Bb * Nn) / 64, 256>>>(x, clusters, bnw, bnb, rm, rv);
    dim3 g2(Dd / 64, Bb);
    k2_vlad<<<g2, 256>>>(x);
    k3_colnorm<<<Bb * Kk, 128>>>(c2, out);
    k4_scale<<<(Bb * Dd * Kk) / 256, 256>>>(out);
}